// round 14
// baseline (speedup 1.0000x reference)
#include <cuda_runtime.h>
#include <cuda_fp16.h>
#include <math.h>
#include <stdint.h>

// Problem dims
#define BB 128
#define HH 600
#define RR 200
#define VV 50257
#define H2 1200
#define H4 2400

#define LDG_GATE 2432
#define LDG_U    1280
#define LDG_NH   1280
#define LDG_LOG  50304
#define NBX      (LDG_LOG/64)    // 786 n-blocks of the big GEMM

// Output offsets
#define OFF_OUTPROB 0
#define OFF_LOGATT  (BB*VV)
#define OFF_PCOPY   (OFF_LOGATT + BB*RR)
#define OFF_NHOUT   (OFF_PCOPY + BB)
#define OFF_NEWCELL (OFF_NHOUT + 2*BB*HH)

// ---------------- scratch ----------------
#define SLICE (128*2560)
__device__ float  d_part[8*SLICE];
__device__ __align__(16) __half d_x_h[BB*HH];
__device__ __align__(16) __half d_cat_h[BB*H4];
__device__ __align__(16) __half d_nh_h[BB*LDG_NH];
__device__ float  d_logits[BB*LDG_LOG];
__device__ float  d_WlinT[H2*H2];
__device__ float  d_smax[BB*NBX];    // per-row per-block softmax max
__device__ float  d_ssum[BB*NBX];    // per-row per-block sum exp

// ---------------- GEMM (tile 128x64, 2 CTAs/SM) ----------------
#define SROWB 144
#define AST   18432
#define WST   9216
#define OFF_W (2*AST)            // 36864
#define GSMEM (OFF_W + 2*WST)    // 55296

__device__ __forceinline__ uint32_t smem_u32_of(const void* p) {
    uint32_t a;
    asm("{ .reg .u64 t; cvta.to.shared.u64 t, %1; cvt.u32.u64 %0, t; }" : "=r"(a) : "l"(p));
    return a;
}
__device__ __forceinline__ void ldsm_x4(uint32_t& r0, uint32_t& r1, uint32_t& r2, uint32_t& r3,
                                        uint32_t addr) {
    asm volatile("ldmatrix.sync.aligned.m8n8.x4.shared.b16 {%0,%1,%2,%3}, [%4];"
                 : "=r"(r0), "=r"(r1), "=r"(r2), "=r"(r3) : "r"(addr));
}
__device__ __forceinline__ void mma16816(float* c, const uint32_t* a, const uint32_t* b) {
    asm volatile("mma.sync.aligned.m16n8k16.row.col.f32.f16.f16.f32 "
                 "{%0,%1,%2,%3}, {%4,%5,%6,%7}, {%8,%9}, {%0,%1,%2,%3};"
                 : "+f"(c[0]), "+f"(c[1]), "+f"(c[2]), "+f"(c[3])
                 : "r"(a[0]), "r"(a[1]), "r"(a[2]), "r"(a[3]), "r"(b[0]), "r"(b[1]));
}

// C[128, 64-tile] = A[128,K](fp16) @ W[N,K]^T(fp32)
struct GemmCore {
    float acc[2][4][4];
    uint4  ra[4];
    float4 rw[4];
    int tid, lane, warp, wm, wn, n0;
    uint32_t sa, aPat, bPat;
    const __half* A; int lda;
    const float* W; int ldw;
    int N, K;
    char* smc;

    __device__ __forceinline__ void init(char* smc_, const __half* A_, int lda_,
                                         const float* W_, int ldw_, int n0_, int N_, int K_) {
        smc = smc_; A = A_; lda = lda_; W = W_; ldw = ldw_; n0 = n0_; N = N_; K = K_;
        tid = threadIdx.x; warp = tid >> 5; lane = tid & 31;
        wm = warp >> 1; wn = warp & 1;
        sa = smem_u32_of(smc);
        aPat = sa + (uint32_t)((wm*32 + (lane & 7) + ((lane >> 3) & 1)*8) * SROWB)
                  + (uint32_t)((lane >> 4) * 16);
        bPat = sa + (uint32_t)OFF_W
                  + (uint32_t)((wn*32 + (lane & 7) + (lane >> 4)*8) * SROWB)
                  + (uint32_t)(((lane >> 3) & 1) * 16);
        #pragma unroll
        for (int mi=0; mi<2; mi++)
            #pragma unroll
            for (int ni=0; ni<4; ni++)
                #pragma unroll
                for (int q=0; q<4; q++) acc[mi][ni][q] = 0.f;
    }

    __device__ __forceinline__ void ldg_tile(int kt) {
        const int k0 = kt * 64;
        #pragma unroll
        for (int i = 0; i < 4; i++) {
            int idx = tid + i*256;
            int row = idx >> 3, c = idx & 7;
            int gk = k0 + c*8;
            if (gk < K) ra[i] = *(const uint4*)(A + (size_t)row*lda + gk);
            else        ra[i] = make_uint4(0,0,0,0);
        }
        #pragma unroll
        for (int i = 0; i < 4; i++) {
            int idx = tid + i*256;
            int row = idx >> 4, c = idx & 15;
            int gk = k0 + c*4;
            int gn = n0 + row;
            if (gk < K && gn < N) rw[i] = *(const float4*)(W + (size_t)gn*ldw + gk);
            else                  rw[i] = make_float4(0.f,0.f,0.f,0.f);
        }
    }

    __device__ __forceinline__ void sts_tile(int s) {
        #pragma unroll
        for (int i = 0; i < 4; i++) {
            int idx = tid + i*256;
            int row = idx >> 3, c = idx & 7;
            *(uint4*)(smc + s*AST + row*SROWB + c*16) = ra[i];
        }
        #pragma unroll
        for (int i = 0; i < 4; i++) {
            int idx = tid + i*256;
            int row = idx >> 4, c = idx & 15;
            __half2 p0 = __floats2half2_rn(rw[i].x, rw[i].y);
            __half2 p1 = __floats2half2_rn(rw[i].z, rw[i].w);
            uint2 v; v.x = *(uint32_t*)&p0; v.y = *(uint32_t*)&p1;
            *(uint2*)(smc + OFF_W + s*WST + row*SROWB + c*8) = v;
        }
    }

    __device__ __forceinline__ void compute(int s) {
        const uint32_t aB = aPat + (uint32_t)(s*AST);
        const uint32_t bB = bPat + (uint32_t)(s*WST);
        #pragma unroll
        for (int ks = 0; ks < 4; ks++) {
            uint32_t af[2][4];
            #pragma unroll
            for (int mb = 0; mb < 2; mb++)
                ldsm_x4(af[mb][0], af[mb][1], af[mb][2], af[mb][3],
                        aB + (uint32_t)(mb*16*SROWB) + (uint32_t)(ks*32));
            uint32_t bf[4][2];
            #pragma unroll
            for (int nb2 = 0; nb2 < 2; nb2++) {
                uint32_t r0, r1, r2, r3;
                ldsm_x4(r0, r1, r2, r3,
                        bB + (uint32_t)(nb2*16*SROWB) + (uint32_t)(ks*32));
                bf[nb2*2+0][0] = r0; bf[nb2*2+0][1] = r1;
                bf[nb2*2+1][0] = r2; bf[nb2*2+1][1] = r3;
            }
            #pragma unroll
            for (int mi = 0; mi < 2; mi++)
                #pragma unroll
                for (int ni = 0; ni < 4; ni++)
                    mma16816(acc[mi][ni], af[mi], bf[ni]);
        }
    }

    // Single-barrier mainloop (hazard-safe; see R12)
    __device__ __forceinline__ void run(int kt0, int kt1) {
        ldg_tile(kt0);
        for (int kt = kt0; kt < kt1; kt++) {
            const int s = (kt - kt0) & 1;
            sts_tile(s);
            __syncthreads();
            if (kt + 1 < kt1) ldg_tile(kt + 1);
            compute(s);
        }
    }

    __device__ __forceinline__ void store(float* C, int ldc) {
        const int er = lane >> 2;
        const int ec = (lane & 3) * 2;
        #pragma unroll
        for (int mi = 0; mi < 2; mi++)
            #pragma unroll
            for (int ni = 0; ni < 4; ni++) {
                int row = wm*32 + mi*16 + er;
                int col = n0 + wn*32 + ni*8 + ec;
                float2 v0; v0.x = acc[mi][ni][0]; v0.y = acc[mi][ni][1];
                float2 v1; v1.x = acc[mi][ni][2]; v1.y = acc[mi][ni][3];
                *(float2*)(C + (size_t)row*ldc + col)     = v0;
                *(float2*)(C + (size_t)(row+8)*ldc + col) = v1;
            }
    }
};

// Big GEMM + per-block softmax stats (max / sum-exp over this block's 64 cols)
__global__ void __launch_bounds__(256, 2) gemm_mma_soft(
    const __half* __restrict__ A, int lda,
    const float* __restrict__ W, int ldw,
    float* __restrict__ C, int ldc, int N, int K,
    const float* __restrict__ bias)
{
    extern __shared__ __align__(16) char smc[];
    GemmCore g;
    g.init(smc, A, lda, W, ldw, blockIdx.x*64, N, K);
    g.run(0, (K + 63) >> 6);
    g.store(C, ldc);

    // ---- softmax stats epilogue ----
    const int lane = g.lane, wn = g.wn, wm = g.wm;
    const int er = lane >> 2;
    const int ec = (lane & 3) * 2;
    const int bx = blockIdx.x;

    // bias + validity for this thread's 8 columns (same for all row contexts)
    float bb[8];
    bool  ok[8];
    #pragma unroll
    for (int ni = 0; ni < 4; ni++)
        #pragma unroll
        for (int j = 0; j < 2; j++) {
            int col = g.n0 + wn*32 + ni*8 + ec + j;
            bool o = col < VV;
            ok[ni*2+j] = o;
            bb[ni*2+j] = o ? bias[col] : 0.f;
        }

    __syncthreads();                       // stage smem now dead -> reuse
    float* smax = (float*)smc;             // [128][2]
    float* ssum = smax + 256;              // [128][2]

    // pass 1: row max
    #pragma unroll
    for (int c = 0; c < 4; c++) {
        const int mi = c >> 1, half = c & 1;
        int row = wm*32 + mi*16 + half*8 + er;
        float m = -INFINITY;
        #pragma unroll
        for (int ni = 0; ni < 4; ni++)
            #pragma unroll
            for (int j = 0; j < 2; j++)
                if (ok[ni*2+j]) m = fmaxf(m, g.acc[mi][ni][half*2+j] + bb[ni*2+j]);
        m = fmaxf(m, __shfl_xor_sync(0xFFFFFFFFu, m, 1));
        m = fmaxf(m, __shfl_xor_sync(0xFFFFFFFFu, m, 2));
        smax[row*2 + wn] = m;
    }
    __syncthreads();
    // pass 2: row sum-exp
    #pragma unroll
    for (int c = 0; c < 4; c++) {
        const int mi = c >> 1, half = c & 1;
        int row = wm*32 + mi*16 + half*8 + er;
        float m = fmaxf(smax[row*2], smax[row*2+1]);
        float s = 0.f;
        #pragma unroll
        for (int ni = 0; ni < 4; ni++)
            #pragma unroll
            for (int j = 0; j < 2; j++)
                if (ok[ni*2+j]) s += expf(g.acc[mi][ni][half*2+j] + bb[ni*2+j] - m);
        s += __shfl_xor_sync(0xFFFFFFFFu, s, 1);
        s += __shfl_xor_sync(0xFFFFFFFFu, s, 2);
        ssum[row*2 + wn] = s;
    }
    __syncthreads();
    // writer: one thread per row
    if (wn == 0 && (lane & 3) == 0) {
        #pragma unroll
        for (int c = 0; c < 4; c++) {
            const int mi = c >> 1, half = c & 1;
            int row = wm*32 + mi*16 + half*8 + er;
            d_smax[(size_t)row*NBX + bx] = fmaxf(smax[row*2], smax[row*2+1]);
            d_ssum[(size_t)row*NBX + bx] = ssum[row*2] + ssum[row*2+1];
        }
    }
}

// Split-K GEMM: grid (nx, nsplit, nW). Partial -> d_part slice (z*nsplit + y).
__global__ void __launch_bounds__(256, 2) gemm_mma_split(
    const __half* __restrict__ A, int lda,
    const float* __restrict__ W0, const float* __restrict__ W1, int ldw,
    int ldc, int N, int K)
{
    extern __shared__ __align__(16) char smc[];
    const float* W = blockIdx.z ? W1 : W0;
    const int nsplit = gridDim.y;
    const int KT = (K + 63) >> 6;
    const int kt0 = (KT * blockIdx.y) / nsplit;
    const int kt1 = (KT * (blockIdx.y + 1)) / nsplit;
    GemmCore g;
    g.init(smc, A, lda, W, ldw, blockIdx.x*64, N, K);
    g.run(kt0, kt1);
    const int slice = blockIdx.z * nsplit + blockIdx.y;
    g.store(d_part + (size_t)slice * SLICE, ldc);
}

// ---------------- transpose W_lin ----------------
__global__ void transpose_wlin(const float* __restrict__ Wl) {
    __shared__ float t[32][33];
    int x = blockIdx.x * 32 + threadIdx.x;
    int y = blockIdx.y * 32 + threadIdx.y;
    if (x < H2 && y < H2) t[threadIdx.y][threadIdx.x] = Wl[(size_t)y * H2 + x];
    __syncthreads();
    int ox = blockIdx.y * 32 + threadIdx.x;
    int oy = blockIdx.x * 32 + threadIdx.y;
    if (ox < H2 && oy < H2) d_WlinT[(size_t)oy * H2 + ox] = t[threadIdx.x][threadIdx.y];
}

// ---------------- small kernels ----------------
__device__ __forceinline__ float sigmoidf_(float x) { return 1.0f / (1.0f + expf(-x)); }

__global__ void gather_emb(const int* __restrict__ word, const float* __restrict__ emb) {
    int idx = blockIdx.x*blockDim.x + threadIdx.x;
    if (idx >= BB*HH) return;
    int b = idx / HH, k = idx % HH;
    d_x_h[idx] = __float2half(emb[(size_t)word[b]*HH + k]);
}

__global__ void lstm_act(const float* __restrict__ bihf, const float* __restrict__ bhhf,
                         const float* __restrict__ bihb, const float* __restrict__ bhhb,
                         float* __restrict__ out_cell) {
    int idx = blockIdx.x*blockDim.x + threadIdx.x;
    if (idx >= BB*HH) return;
    int b = idx / HH, j = idx % HH;
    #pragma unroll
    for (int z = 0; z < 2; z++) {
        const float* bih = z ? bihb : bihf;
        const float* bhh = z ? bhhb : bhhf;
        float i_ = 0.f, gg = 0.f, o_ = 0.f;
        #pragma unroll
        for (int s = 0; s < 4; s++) {
            const float* g = d_part + (size_t)(z*4+s)*SLICE + (size_t)b*LDG_GATE;
            i_ += g[j]; gg += g[H2 + j]; o_ += g[1800 + j];
        }
        i_ += bih[j]        + bhh[j];
        gg += bih[H2 + j]   + bhh[H2 + j];
        o_ += bih[1800 + j] + bhh[1800 + j];
        float c = sigmoidf_(i_) * tanhf(gg);
        float h = sigmoidf_(o_) * tanhf(c);
        d_cat_h[b*H4 + z*HH + j] = __float2half(h);
        out_cell[z*BB*HH + b*HH + j] = c;
    }
}

// ---------------- flash-style attention: ONE pass over encoded ----------------
#define ATT_CH     16
#define ATT_RSTR   1208
#define ATT_OFF_SU   (ATT_CH*ATT_RSTR)
#define ATT_OFF_SC   (ATT_OFF_SU + 1200)
#define ATT_OFF_WT   (ATT_OFF_SC + 208)
#define ATT_OFF_CTL  (ATT_OFF_WT + 16)
#define ATT_SMEM   ((ATT_OFF_CTL + 4) * 4)

__global__ void __launch_bounds__(512) attn_flash(const float* __restrict__ enc,
                                                  float* __restrict__ log_att_out) {
    extern __shared__ float smf[];
    float* srow   = smf;
    float* su     = smf + ATT_OFF_SU;
    float* sscore = smf + ATT_OFF_SC;
    float* swt    = smf + ATT_OFF_WT;
    float* sctl   = smf + ATT_OFF_CTL;
    const int b = blockIdx.x, tid = threadIdx.x;
    const int warp = tid >> 5, lane = tid & 31;

    for (int k = tid; k < H2; k += 512) {
        float s = 0.f;
        #pragma unroll
        for (int p = 0; p < 8; p++) s += d_part[(size_t)p*SLICE + (size_t)b*LDG_U + k];
        su[k] = s;
    }
    if (tid == 0) { sctl[1] = -INFINITY; sctl[2] = 0.f; }
    __syncthreads();

    float2 sureg[19];
    #pragma unroll
    for (int i = 0; i < 19; i++) {
        int j = lane + 32*i;
        sureg[i] = (j < 600) ? ((const float2*)su)[j] : make_float2(0.f, 0.f);
    }

    float2 acc0 = make_float2(0.f, 0.f), acc1 = make_float2(0.f, 0.f);
    const int d2a = tid;
    const int d2b = tid + 512;

    for (int c = 0; c < (RR + ATT_CH - 1)/ATT_CH; c++) {
        const int r0 = c * ATT_CH;
        const int nr = min(ATT_CH, RR - r0);

        for (int idx = tid; idx < nr*600; idx += 512) {
            int r = idx / 600, j = idx % 600;
            ((float2*)(srow + r*ATT_RSTR))[j] =
                ((const float2*)(enc + ((size_t)b*RR + r0 + r)*H2))[j];
        }
        __syncthreads();

        if (warp < nr) {
            const float2* row = (const float2*)(srow + warp*ATT_RSTR);
            float s = 0.f;
            #pragma unroll
            for (int i = 0; i < 19; i++) {
                int j = lane + 32*i;
                if (j < 600) {
                    float2 e = row[j];
                    s += e.x*sureg[i].x + e.y*sureg[i].y;
                }
            }
            #pragma unroll
            for (int o = 16; o > 0; o >>= 1) s += __shfl_xor_sync(0xFFFFFFFFu, s, o);
            if (lane == 0) sscore[r0 + warp] = s;
        }
        __syncthreads();

        if (warp == 0) {
            float m_old = sctl[1];
            float s = (lane < nr) ? sscore[r0 + lane] : -INFINITY;
            float cmax = s;
            #pragma unroll
            for (int o = 16; o > 0; o >>= 1)
                cmax = fmaxf(cmax, __shfl_xor_sync(0xFFFFFFFFu, cmax, o));
            float m_new = fmaxf(m_old, cmax);
            float w = (lane < nr) ? expf(s - m_new) : 0.f;
            float csum = w;
            #pragma unroll
            for (int o = 16; o > 0; o >>= 1) csum += __shfl_xor_sync(0xFFFFFFFFu, csum, o);
            if (lane < ATT_CH) swt[lane] = w;
            if (lane == 0) {
                float l_old = sctl[2];
                float factor = expf(m_old - m_new);
                sctl[0] = factor;
                sctl[1] = m_new;
                sctl[2] = l_old*factor + csum;
            }
        }
        __syncthreads();

        {
            float f = sctl[0];
            acc0.x *= f; acc0.y *= f; acc1.x *= f; acc1.y *= f;
            if (d2a < 600) {
                for (int r = 0; r < nr; r++) {
                    float wr = swt[r];
                    float2 e = ((const float2*)(srow + r*ATT_RSTR))[d2a];
                    acc0.x += wr*e.x; acc0.y += wr*e.y;
                }
            }
            if (d2b < 600) {
                for (int r = 0; r < nr; r++) {
                    float wr = swt[r];
                    float2 e = ((const float2*)(srow + r*ATT_RSTR))[d2b];
                    acc1.x += wr*e.x; acc1.y += wr*e.y;
                }
            }
        }
        __syncthreads();
    }

    const float lse = sctl[1] + logf(sctl[2]);
    const float inv = 1.f / sctl[2];
    for (int r = tid; r < RR; r += 512)
        log_att_out[(size_t)b*RR + r] = sscore[r] - lse;
    __half2* dst = (__half2*)(d_cat_h + (size_t)b*H4 + H2);
    if (d2a < 600) dst[d2a] = __floats2half2_rn(acc0.x*inv, acc0.y*inv);
    if (d2b < 600) dst[d2b] = __floats2half2_rn(acc1.x*inv, acc1.y*inv);
}

__global__ void nh_act(const float* __restrict__ b_tanh, float* __restrict__ nh_out) {
    int idx = blockIdx.x*blockDim.x + threadIdx.x;
    if (idx >= BB*H2) return;
    int b = idx / H2, j = idx % H2;
    float v = b_tanh[j];
    #pragma unroll
    for (int p = 0; p < 8; p++) v += d_part[(size_t)p*SLICE + (size_t)b*LDG_NH + j];
    v = tanhf(v);
    d_nh_h[(size_t)b*LDG_NH + j] = __float2half(v);
    int s = j / HH, hh = j % HH;
    nh_out[s*BB*HH + b*HH + hh] = v;
}

__global__ void pcopy_kernel(const float* __restrict__ W_sig, const float* __restrict__ b_sig,
                             float* __restrict__ out) {
    int w = (blockIdx.x*blockDim.x + threadIdx.x) >> 5;
    int lane = threadIdx.x & 31;
    if (w >= BB) return;
    const __half* nh = d_nh_h + (size_t)w*LDG_NH;
    float s = 0.f;
    for (int k = lane; k < H2; k += 32) s += __half2float(nh[k])*W_sig[k];
    #pragma unroll
    for (int o = 16; o > 0; o >>= 1) s += __shfl_xor_sync(0xFFFFFFFFu, s, o);
    if (lane == 0) out[w] = sigmoidf_(s + b_sig[0]);
}

// combine per-block stats + single sweep: out = logits + bias - lse
__global__ void __launch_bounds__(1024) logsoftmax2(const float* __restrict__ bias,
                                                    float* __restrict__ out) {
    __shared__ float red[1024];
    const int b = blockIdx.x, t = threadIdx.x;
    float m = (t < NBX) ? d_smax[(size_t)b*NBX + t] : -INFINITY;
    red[t] = m; __syncthreads();
    for (int s = 512; s > 0; s >>= 1) { if (t < s) red[t] = fmaxf(red[t], red[t+s]); __syncthreads(); }
    m = red[0]; __syncthreads();
    float sum = (t < NBX) ? d_ssum[(size_t)b*NBX + t] * expf(d_smax[(size_t)b*NBX + t] - m) : 0.f;
    red[t] = sum; __syncthreads();
    for (int s = 512; s > 0; s >>= 1) { if (t < s) red[t] += red[t+s]; __syncthreads(); }
    const float lse = m + logf(red[0]);
    const float* x = d_logits + (size_t)b*LDG_LOG;
    for (int v = t; v < VV; v += 1024)
        out[(size_t)b*VV + v] = x[v] + bias[v] - lse;
}

// ---------------- launch ----------------
extern "C" void kernel_launch(void* const* d_in, const int* in_sizes, int n_in,
                              void* d_out, int out_size)
{
    const int*   word   = (const int*)  d_in[0];
    const float* enc    = (const float*)d_in[3];
    const float* emb    = (const float*)d_in[4];
    const float* W_ih_f = (const float*)d_in[5];
    const float* b_ih_f = (const float*)d_in[7];
    const float* b_hh_f = (const float*)d_in[8];
    const float* W_ih_b = (const float*)d_in[9];
    const float* b_ih_b = (const float*)d_in[11];
    const float* b_hh_b = (const float*)d_in[12];
    const float* W_lin  = (const float*)d_in[13];
    const float* W_tanh = (const float*)d_in[15];
    const float* b_tanh = (const float*)d_in[16];
    const float* W_soft = (const float*)d_in[17];
    const float* b_soft = (const float*)d_in[18];
    const float* W_sig  = (const float*)d_in[19];
    const float* b_sig  = (const float*)d_in[20];

    float* out = (float*)d_out;

    __half *px, *pcat, *pnh;
    float *plog, *pWlT;
    cudaGetSymbolAddress((void**)&px,   d_x_h);
    cudaGetSymbolAddress((void**)&pcat, d_cat_h);
    cudaGetSymbolAddress((void**)&pnh,  d_nh_h);
    cudaGetSymbolAddress((void**)&plog, d_logits);
    cudaGetSymbolAddress((void**)&pWlT, d_WlinT);

    cudaFuncSetAttribute(gemm_mma_soft,  cudaFuncAttributeMaxDynamicSharedMemorySize, GSMEM);
    cudaFuncSetAttribute(gemm_mma_split, cudaFuncAttributeMaxDynamicSharedMemorySize, GSMEM);
    cudaFuncSetAttribute(attn_flash,     cudaFuncAttributeMaxDynamicSharedMemorySize, ATT_SMEM);

    // 1. embedding gather + W_lin transpose
    gather_emb<<<(BB*HH + 255)/256, 256>>>(word, emb);
    transpose_wlin<<<dim3(38,38), dim3(32,32)>>>(W_lin);

    // 2. both gate GEMMs, split-K x4 x 2 dirs (304 blocks, 2 CTA/SM)
    gemm_mma_split<<<dim3(LDG_GATE/64,4,2), 256, GSMEM>>>(px, HH, W_ih_f, W_ih_b, HH,
                                                          LDG_GATE, H4, HH);

    // 3. LSTM activations (sums partials)
    lstm_act<<<(BB*HH + 255)/256, 256>>>(b_ih_f, b_hh_f, b_ih_b, b_hh_b, out + OFF_NEWCELL);

    // 4. u = h @ W_lin, split-K x8 (160 blocks)
    gemm_mma_split<<<dim3(LDG_U/64,8,1), 256, GSMEM>>>(pcat, H4, pWlT, pWlT, H2,
                                                       LDG_U, H2, H2);

    // 5. flash attention: single pass over encoded
    attn_flash<<<BB, 512, ATT_SMEM>>>(enc, out + OFF_LOGATT);

    // 6. nh_raw = cat @ W_tanh^T, split-K x8 (160 blocks)
    gemm_mma_split<<<dim3(LDG_NH/64,8,1), 256, GSMEM>>>(pcat, H4, W_tanh, W_tanh, H4,
                                                        LDG_NH, H2, H4);

    // 7. nh activation + nh_out
    nh_act<<<(BB*H2 + 255)/256, 256>>>(b_tanh, out + OFF_NHOUT);

    // 8. p_copy
    pcopy_kernel<<<(BB*32 + 255)/256, 256>>>(W_sig, b_sig, out + OFF_PCOPY);

    // 9. logits = nh @ W_soft^T + softmax stats (786 blocks)
    gemm_mma_soft<<<NBX, 256, GSMEM>>>(pnh, LDG_NH, W_soft, H2, plog, LDG_LOG, VV, H2,
                                       b_soft);

    // 10. combine stats + single-pass log_softmax
    logsoftmax2<<<BB, 1024>>>(b_soft, out + OFF_OUTPROB);
}

// round 16
// speedup vs baseline: 1.0467x; 1.0467x over previous
#include <cuda_runtime.h>
#include <cuda_fp16.h>
#include <math.h>
#include <stdint.h>

// Problem dims
#define BB 128
#define HH 600
#define RR 200
#define VV 50257
#define H2 1200
#define H4 2400

#define LDG_GATE 2432
#define LDG_U    1280
#define LDG_NH   1280
#define LDG_LOG  50304

// Output offsets
#define OFF_OUTPROB 0
#define OFF_LOGATT  (BB*VV)
#define OFF_PCOPY   (OFF_LOGATT + BB*RR)
#define OFF_NHOUT   (OFF_PCOPY + BB)
#define OFF_NEWCELL (OFF_NHOUT + 2*BB*HH)

// ---------------- scratch ----------------
#define SLICE (128*2560)
__device__ float  d_part[8*SLICE];
__device__ __align__(16) __half d_x_h[BB*HH];
__device__ __align__(16) __half d_cat_h[BB*H4];
__device__ __align__(16) __half d_nh_h[BB*LDG_NH];
__device__ float  d_logits[BB*LDG_LOG];
__device__ float  d_WlinT[H2*H2];

// ---------------- GEMM (tile 128x64, 2 CTAs/SM) ----------------
#define SROWB 144
#define AST   18432
#define WST   9216
#define OFF_W (2*AST)            // 36864
#define GSMEM (OFF_W + 2*WST)    // 55296

__device__ __forceinline__ uint32_t smem_u32_of(const void* p) {
    uint32_t a;
    asm("{ .reg .u64 t; cvta.to.shared.u64 t, %1; cvt.u32.u64 %0, t; }" : "=r"(a) : "l"(p));
    return a;
}
__device__ __forceinline__ void ldsm_x4(uint32_t& r0, uint32_t& r1, uint32_t& r2, uint32_t& r3,
                                        uint32_t addr) {
    asm volatile("ldmatrix.sync.aligned.m8n8.x4.shared.b16 {%0,%1,%2,%3}, [%4];"
                 : "=r"(r0), "=r"(r1), "=r"(r2), "=r"(r3) : "r"(addr));
}
__device__ __forceinline__ void mma16816(float* c, const uint32_t* a, const uint32_t* b) {
    asm volatile("mma.sync.aligned.m16n8k16.row.col.f32.f16.f16.f32 "
                 "{%0,%1,%2,%3}, {%4,%5,%6,%7}, {%8,%9}, {%0,%1,%2,%3};"
                 : "+f"(c[0]), "+f"(c[1]), "+f"(c[2]), "+f"(c[3])
                 : "r"(a[0]), "r"(a[1]), "r"(a[2]), "r"(a[3]), "r"(b[0]), "r"(b[1]));
}

// C[128, 64-tile] = A[128,K](fp16) @ W[N,K]^T(fp32)
struct GemmCore {
    float acc[2][4][4];
    uint4  ra[4];
    float4 rw[4];
    int tid, lane, warp, wm, wn, n0;
    uint32_t sa, aPat, bPat;
    const __half* A; int lda;
    const float* W; int ldw;
    int N, K;
    char* smc;

    __device__ __forceinline__ void init(char* smc_, const __half* A_, int lda_,
                                         const float* W_, int ldw_, int n0_, int N_, int K_) {
        smc = smc_; A = A_; lda = lda_; W = W_; ldw = ldw_; n0 = n0_; N = N_; K = K_;
        tid = threadIdx.x; warp = tid >> 5; lane = tid & 31;
        wm = warp >> 1; wn = warp & 1;
        sa = smem_u32_of(smc);
        aPat = sa + (uint32_t)((wm*32 + (lane & 7) + ((lane >> 3) & 1)*8) * SROWB)
                  + (uint32_t)((lane >> 4) * 16);
        bPat = sa + (uint32_t)OFF_W
                  + (uint32_t)((wn*32 + (lane & 7) + (lane >> 4)*8) * SROWB)
                  + (uint32_t)(((lane >> 3) & 1) * 16);
        #pragma unroll
        for (int mi=0; mi<2; mi++)
            #pragma unroll
            for (int ni=0; ni<4; ni++)
                #pragma unroll
                for (int q=0; q<4; q++) acc[mi][ni][q] = 0.f;
    }

    __device__ __forceinline__ void ldg_tile(int kt) {
        const int k0 = kt * 64;
        #pragma unroll
        for (int i = 0; i < 4; i++) {
            int idx = tid + i*256;
            int row = idx >> 3, c = idx & 7;
            int gk = k0 + c*8;
            if (gk < K) ra[i] = *(const uint4*)(A + (size_t)row*lda + gk);
            else        ra[i] = make_uint4(0,0,0,0);
        }
        #pragma unroll
        for (int i = 0; i < 4; i++) {
            int idx = tid + i*256;
            int row = idx >> 4, c = idx & 15;
            int gk = k0 + c*4;
            int gn = n0 + row;
            if (gk < K && gn < N) rw[i] = *(const float4*)(W + (size_t)gn*ldw + gk);
            else                  rw[i] = make_float4(0.f,0.f,0.f,0.f);
        }
    }

    __device__ __forceinline__ void sts_tile(int s) {
        #pragma unroll
        for (int i = 0; i < 4; i++) {
            int idx = tid + i*256;
            int row = idx >> 3, c = idx & 7;
            *(uint4*)(smc + s*AST + row*SROWB + c*16) = ra[i];
        }
        #pragma unroll
        for (int i = 0; i < 4; i++) {
            int idx = tid + i*256;
            int row = idx >> 4, c = idx & 15;
            __half2 p0 = __floats2half2_rn(rw[i].x, rw[i].y);
            __half2 p1 = __floats2half2_rn(rw[i].z, rw[i].w);
            uint2 v; v.x = *(uint32_t*)&p0; v.y = *(uint32_t*)&p1;
            *(uint2*)(smc + OFF_W + s*WST + row*SROWB + c*8) = v;
        }
    }

    __device__ __forceinline__ void compute(int s) {
        const uint32_t aB = aPat + (uint32_t)(s*AST);
        const uint32_t bB = bPat + (uint32_t)(s*WST);
        #pragma unroll
        for (int ks = 0; ks < 4; ks++) {
            uint32_t af[2][4];
            #pragma unroll
            for (int mb = 0; mb < 2; mb++)
                ldsm_x4(af[mb][0], af[mb][1], af[mb][2], af[mb][3],
                        aB + (uint32_t)(mb*16*SROWB) + (uint32_t)(ks*32));
            uint32_t bf[4][2];
            #pragma unroll
            for (int nb2 = 0; nb2 < 2; nb2++) {
                uint32_t r0, r1, r2, r3;
                ldsm_x4(r0, r1, r2, r3,
                        bB + (uint32_t)(nb2*16*SROWB) + (uint32_t)(ks*32));
                bf[nb2*2+0][0] = r0; bf[nb2*2+0][1] = r1;
                bf[nb2*2+1][0] = r2; bf[nb2*2+1][1] = r3;
            }
            #pragma unroll
            for (int mi = 0; mi < 2; mi++)
                #pragma unroll
                for (int ni = 0; ni < 4; ni++)
                    mma16816(acc[mi][ni], af[mi], bf[ni]);
        }
    }

    // Single-barrier mainloop (hazard-safe; see R12)
    __device__ __forceinline__ void run(int kt0, int kt1) {
        ldg_tile(kt0);
        for (int kt = kt0; kt < kt1; kt++) {
            const int s = (kt - kt0) & 1;
            sts_tile(s);
            __syncthreads();
            if (kt + 1 < kt1) ldg_tile(kt + 1);
            compute(s);
        }
    }

    __device__ __forceinline__ void store(float* C, int ldc) {
        const int er = lane >> 2;
        const int ec = (lane & 3) * 2;
        #pragma unroll
        for (int mi = 0; mi < 2; mi++)
            #pragma unroll
            for (int ni = 0; ni < 4; ni++) {
                int row = wm*32 + mi*16 + er;
                int col = n0 + wn*32 + ni*8 + ec;
                float2 v0; v0.x = acc[mi][ni][0]; v0.y = acc[mi][ni][1];
                float2 v1; v1.x = acc[mi][ni][2]; v1.y = acc[mi][ni][3];
                *(float2*)(C + (size_t)row*ldc + col)     = v0;
                *(float2*)(C + (size_t)(row+8)*ldc + col) = v1;
            }
    }
};

// Direct GEMM (big W_soft)
__global__ void __launch_bounds__(256, 2) gemm_mma(
    const __half* __restrict__ A, int lda,
    const float* __restrict__ W, int ldw,
    float* __restrict__ C, int ldc, int N, int K)
{
    extern __shared__ __align__(16) char smc[];
    GemmCore g;
    g.init(smc, A, lda, W, ldw, blockIdx.x*64, N, K);
    g.run(0, (K + 63) >> 6);
    g.store(C, ldc);
}

// Split-K GEMM: grid (nx, nsplit, nW). Partial -> d_part slice (z*nsplit + y).
__global__ void __launch_bounds__(256, 2) gemm_mma_split(
    const __half* __restrict__ A, int lda,
    const float* __restrict__ W0, const float* __restrict__ W1, int ldw,
    int ldc, int N, int K)
{
    extern __shared__ __align__(16) char smc[];
    const float* W = blockIdx.z ? W1 : W0;
    const int nsplit = gridDim.y;
    const int KT = (K + 63) >> 6;
    const int kt0 = (KT * blockIdx.y) / nsplit;
    const int kt1 = (KT * (blockIdx.y + 1)) / nsplit;
    GemmCore g;
    g.init(smc, A, lda, W, ldw, blockIdx.x*64, N, K);
    g.run(kt0, kt1);
    const int slice = blockIdx.z * nsplit + blockIdx.y;
    g.store(d_part + (size_t)slice * SLICE, ldc);
}

// ---------------- transpose W_lin ----------------
__global__ void transpose_wlin(const float* __restrict__ Wl) {
    __shared__ float t[32][33];
    int x = blockIdx.x * 32 + threadIdx.x;
    int y = blockIdx.y * 32 + threadIdx.y;
    if (x < H2 && y < H2) t[threadIdx.y][threadIdx.x] = Wl[(size_t)y * H2 + x];
    __syncthreads();
    int ox = blockIdx.y * 32 + threadIdx.x;
    int oy = blockIdx.x * 32 + threadIdx.y;
    if (ox < H2 && oy < H2) d_WlinT[(size_t)oy * H2 + ox] = t[threadIdx.x][threadIdx.y];
}

// ---------------- small kernels ----------------
__device__ __forceinline__ float sigmoidf_(float x) { return 1.0f / (1.0f + expf(-x)); }

__global__ void gather_emb(const int* __restrict__ word, const float* __restrict__ emb) {
    int idx = blockIdx.x*blockDim.x + threadIdx.x;
    if (idx >= BB*HH) return;
    int b = idx / HH, k = idx % HH;
    d_x_h[idx] = __float2half(emb[(size_t)word[b]*HH + k]);
}

// gates unsplit: slice z holds the full pre-bias gates for direction z
__global__ void lstm_act(const float* __restrict__ bihf, const float* __restrict__ bhhf,
                         const float* __restrict__ bihb, const float* __restrict__ bhhb,
                         float* __restrict__ out_cell) {
    int idx = blockIdx.x*blockDim.x + threadIdx.x;
    if (idx >= BB*HH) return;
    int b = idx / HH, j = idx % HH;
    #pragma unroll
    for (int z = 0; z < 2; z++) {
        const float* bih = z ? bihb : bihf;
        const float* bhh = z ? bhhb : bhhf;
        const float* g = d_part + (size_t)z*SLICE + (size_t)b*LDG_GATE;
        float i_ = g[j]        + bih[j]        + bhh[j];
        float gg = g[H2 + j]   + bih[H2 + j]   + bhh[H2 + j];
        float o_ = g[1800 + j] + bih[1800 + j] + bhh[1800 + j];
        float c = sigmoidf_(i_) * tanhf(gg);
        float h = sigmoidf_(o_) * tanhf(c);
        d_cat_h[b*H4 + z*HH + j] = __float2half(h);
        out_cell[z*BB*HH + b*HH + j] = c;
    }
}

// ---------------- flash-style attention: ONE pass over encoded ----------------
#define ATT_CH     16
#define ATT_RSTR   1208
#define ATT_OFF_SU   (ATT_CH*ATT_RSTR)
#define ATT_OFF_SC   (ATT_OFF_SU + 1200)
#define ATT_OFF_WT   (ATT_OFF_SC + 208)
#define ATT_OFF_CTL  (ATT_OFF_WT + 16)
#define ATT_SMEM   ((ATT_OFF_CTL + 4) * 4)

__global__ void __launch_bounds__(512) attn_flash(const float* __restrict__ enc,
                                                  float* __restrict__ log_att_out) {
    extern __shared__ float smf[];
    float* srow   = smf;
    float* su     = smf + ATT_OFF_SU;
    float* sscore = smf + ATT_OFF_SC;
    float* swt    = smf + ATT_OFF_WT;
    float* sctl   = smf + ATT_OFF_CTL;
    const int b = blockIdx.x, tid = threadIdx.x;
    const int warp = tid >> 5, lane = tid & 31;

    for (int k = tid; k < H2; k += 512) {
        float s = 0.f;
        #pragma unroll
        for (int p = 0; p < 8; p++) s += d_part[(size_t)p*SLICE + (size_t)b*LDG_U + k];
        su[k] = s;
    }
    if (tid == 0) { sctl[1] = -INFINITY; sctl[2] = 0.f; }
    __syncthreads();

    float2 sureg[19];
    #pragma unroll
    for (int i = 0; i < 19; i++) {
        int j = lane + 32*i;
        sureg[i] = (j < 600) ? ((const float2*)su)[j] : make_float2(0.f, 0.f);
    }

    float2 acc0 = make_float2(0.f, 0.f), acc1 = make_float2(0.f, 0.f);
    const int d2a = tid;
    const int d2b = tid + 512;

    for (int c = 0; c < (RR + ATT_CH - 1)/ATT_CH; c++) {
        const int r0 = c * ATT_CH;
        const int nr = min(ATT_CH, RR - r0);

        for (int idx = tid; idx < nr*600; idx += 512) {
            int r = idx / 600, j = idx % 600;
            ((float2*)(srow + r*ATT_RSTR))[j] =
                ((const float2*)(enc + ((size_t)b*RR + r0 + r)*H2))[j];
        }
        __syncthreads();

        if (warp < nr) {
            const float2* row = (const float2*)(srow + warp*ATT_RSTR);
            float s = 0.f;
            #pragma unroll
            for (int i = 0; i < 19; i++) {
                int j = lane + 32*i;
                if (j < 600) {
                    float2 e = row[j];
                    s += e.x*sureg[i].x + e.y*sureg[i].y;
                }
            }
            #pragma unroll
            for (int o = 16; o > 0; o >>= 1) s += __shfl_xor_sync(0xFFFFFFFFu, s, o);
            if (lane == 0) sscore[r0 + warp] = s;
        }
        __syncthreads();

        if (warp == 0) {
            float m_old = sctl[1];
            float s = (lane < nr) ? sscore[r0 + lane] : -INFINITY;
            float cmax = s;
            #pragma unroll
            for (int o = 16; o > 0; o >>= 1)
                cmax = fmaxf(cmax, __shfl_xor_sync(0xFFFFFFFFu, cmax, o));
            float m_new = fmaxf(m_old, cmax);
            float w = (lane < nr) ? expf(s - m_new) : 0.f;
            float csum = w;
            #pragma unroll
            for (int o = 16; o > 0; o >>= 1) csum += __shfl_xor_sync(0xFFFFFFFFu, csum, o);
            if (lane < ATT_CH) swt[lane] = w;
            if (lane == 0) {
                float l_old = sctl[2];
                float factor = expf(m_old - m_new);
                sctl[0] = factor;
                sctl[1] = m_new;
                sctl[2] = l_old*factor + csum;
            }
        }
        __syncthreads();

        {
            float f = sctl[0];
            acc0.x *= f; acc0.y *= f; acc1.x *= f; acc1.y *= f;
            if (d2a < 600) {
                for (int r = 0; r < nr; r++) {
                    float wr = swt[r];
                    float2 e = ((const float2*)(srow + r*ATT_RSTR))[d2a];
                    acc0.x += wr*e.x; acc0.y += wr*e.y;
                }
            }
            if (d2b < 600) {
                for (int r = 0; r < nr; r++) {
                    float wr = swt[r];
                    float2 e = ((const float2*)(srow + r*ATT_RSTR))[d2b];
                    acc1.x += wr*e.x; acc1.y += wr*e.y;
                }
            }
        }
        __syncthreads();
    }

    const float lse = sctl[1] + logf(sctl[2]);
    const float inv = 1.f / sctl[2];
    for (int r = tid; r < RR; r += 512)
        log_att_out[(size_t)b*RR + r] = sscore[r] - lse;
    __half2* dst = (__half2*)(d_cat_h + (size_t)b*H4 + H2);
    if (d2a < 600) dst[d2a] = __floats2half2_rn(acc0.x*inv, acc0.y*inv);
    if (d2b < 600) dst[d2b] = __floats2half2_rn(acc1.x*inv, acc1.y*inv);
}

__global__ void nh_act(const float* __restrict__ b_tanh, float* __restrict__ nh_out) {
    int idx = blockIdx.x*blockDim.x + threadIdx.x;
    if (idx >= BB*H2) return;
    int b = idx / H2, j = idx % H2;
    float v = b_tanh[j];
    #pragma unroll
    for (int p = 0; p < 8; p++) v += d_part[(size_t)p*SLICE + (size_t)b*LDG_NH + j];
    v = tanhf(v);
    d_nh_h[(size_t)b*LDG_NH + j] = __float2half(v);
    int s = j / HH, hh = j % HH;
    nh_out[s*BB*HH + b*HH + hh] = v;
}

__global__ void pcopy_kernel(const float* __restrict__ W_sig, const float* __restrict__ b_sig,
                             float* __restrict__ out) {
    int w = (blockIdx.x*blockDim.x + threadIdx.x) >> 5;
    int lane = threadIdx.x & 31;
    if (w >= BB) return;
    const __half* nh = d_nh_h + (size_t)w*LDG_NH;
    float s = 0.f;
    for (int k = lane; k < H2; k += 32) s += __half2float(nh[k])*W_sig[k];
    #pragma unroll
    for (int o = 16; o > 0; o >>= 1) s += __shfl_xor_sync(0xFFFFFFFFu, s, o);
    if (lane == 0) out[w] = sigmoidf_(s + b_sig[0]);
}

#define LS_SMEM ((LDG_LOG + 1024) * 4)
__global__ void __launch_bounds__(1024) logsoftmax_v(const float* __restrict__ b_soft,
                                                     float* __restrict__ out) {
    extern __shared__ float sx[];
    float* red = sx + LDG_LOG;
    const int b = blockIdx.x, t = threadIdx.x;
    const float* x = d_logits + (size_t)b*LDG_LOG;
    float mx = -INFINITY;
    for (int v = t; v < VV; v += 1024) {
        float val = x[v] + b_soft[v];
        sx[v] = val;
        mx = fmaxf(mx, val);
    }
    red[t] = mx; __syncthreads();
    for (int s = 512; s > 0; s >>= 1) { if (t < s) red[t] = fmaxf(red[t], red[t+s]); __syncthreads(); }
    mx = red[0]; __syncthreads();
    float sum = 0.f;
    for (int v = t; v < VV; v += 1024) sum += expf(sx[v] - mx);
    red[t] = sum; __syncthreads();
    for (int s = 512; s > 0; s >>= 1) { if (t < s) red[t] += red[t+s]; __syncthreads(); }
    float lse = mx + logf(red[0]);
    for (int v = t; v < VV; v += 1024) out[(size_t)b*VV + v] = sx[v] - lse;
}

// ---------------- launch ----------------
extern "C" void kernel_launch(void* const* d_in, const int* in_sizes, int n_in,
                              void* d_out, int out_size)
{
    const int*   word   = (const int*)  d_in[0];
    const float* enc    = (const float*)d_in[3];
    const float* emb    = (const float*)d_in[4];
    const float* W_ih_f = (const float*)d_in[5];
    const float* b_ih_f = (const float*)d_in[7];
    const float* b_hh_f = (const float*)d_in[8];
    const float* W_ih_b = (const float*)d_in[9];
    const float* b_ih_b = (const float*)d_in[11];
    const float* b_hh_b = (const float*)d_in[12];
    const float* W_lin  = (const float*)d_in[13];
    const float* W_tanh = (const float*)d_in[15];
    const float* b_tanh = (const float*)d_in[16];
    const float* W_soft = (const float*)d_in[17];
    const float* b_soft = (const float*)d_in[18];
    const float* W_sig  = (const float*)d_in[19];
    const float* b_sig  = (const float*)d_in[20];

    float* out = (float*)d_out;

    __half *px, *pcat, *pnh;
    float *plog, *pWlT;
    cudaGetSymbolAddress((void**)&px,   d_x_h);
    cudaGetSymbolAddress((void**)&pcat, d_cat_h);
    cudaGetSymbolAddress((void**)&pnh,  d_nh_h);
    cudaGetSymbolAddress((void**)&plog, d_logits);
    cudaGetSymbolAddress((void**)&pWlT, d_WlinT);

    cudaFuncSetAttribute(gemm_mma,       cudaFuncAttributeMaxDynamicSharedMemorySize, GSMEM);
    cudaFuncSetAttribute(gemm_mma_split, cudaFuncAttributeMaxDynamicSharedMemorySize, GSMEM);
    cudaFuncSetAttribute(logsoftmax_v,   cudaFuncAttributeMaxDynamicSharedMemorySize, LS_SMEM);
    cudaFuncSetAttribute(attn_flash,     cudaFuncAttributeMaxDynamicSharedMemorySize, ATT_SMEM);

    // 1. embedding gather + W_lin transpose
    gather_emb<<<(BB*HH + 255)/256, 256>>>(word, emb);
    transpose_wlin<<<dim3(38,38), dim3(32,32)>>>(W_lin);

    // 2. both gate GEMMs, UNSPLIT (76 blocks fit in one 2-CTA/SM wave)
    gemm_mma_split<<<dim3(LDG_GATE/64,1,2), 256, GSMEM>>>(px, HH, W_ih_f, W_ih_b, HH,
                                                          LDG_GATE, H4, HH);

    // 3. LSTM activations (single slice per direction)
    lstm_act<<<(BB*HH + 255)/256, 256>>>(b_ih_f, b_hh_f, b_ih_b, b_hh_b, out + OFF_NEWCELL);

    // 4. u = h @ W_lin, split-K x8 (160 blocks)
    gemm_mma_split<<<dim3(LDG_U/64,8,1), 256, GSMEM>>>(pcat, H4, pWlT, pWlT, H2,
                                                       LDG_U, H2, H2);

    // 5. flash attention: single pass over encoded
    attn_flash<<<BB, 512, ATT_SMEM>>>(enc, out + OFF_LOGATT);

    // 6. nh_raw = cat @ W_tanh^T, split-K x8 (160 blocks)
    gemm_mma_split<<<dim3(LDG_NH/64,8,1), 256, GSMEM>>>(pcat, H4, W_tanh, W_tanh, H4,
                                                        LDG_NH, H2, H4);

    // 7. nh activation + nh_out
    nh_act<<<(BB*H2 + 255)/256, 256>>>(b_tanh, out + OFF_NHOUT);

    // 8. p_copy
    pcopy_kernel<<<(BB*32 + 255)/256, 256>>>(W_sig, b_sig, out + OFF_PCOPY);

    // 9. logits = nh @ W_soft^T (786 blocks)
    gemm_mma<<<LDG_LOG/64, 256, GSMEM>>>(pnh, LDG_NH, W_soft, H2, plog, LDG_LOG, VV, H2);

    // 10. log_softmax over V (smem-cached, single read+write)
    logsoftmax_v<<<BB, 1024, LS_SMEM>>>(b_soft, out + OFF_OUTPROB);
}

// round 17
// speedup vs baseline: 1.2635x; 1.2071x over previous
#include <cuda_runtime.h>
#include <cuda_fp16.h>
#include <math.h>
#include <stdint.h>

// Problem dims
#define BB 128
#define HH 600
#define RR 200
#define VV 50257
#define H2 1200
#define H4 2400

#define LDG_GATE 2432
#define LDG_U    1280
#define LDG_NH   1280
#define LDG_LOG  50304

// Output offsets
#define OFF_OUTPROB 0
#define OFF_LOGATT  (BB*VV)
#define OFF_PCOPY   (OFF_LOGATT + BB*RR)
#define OFF_NHOUT   (OFF_PCOPY + BB)
#define OFF_NEWCELL (OFF_NHOUT + 2*BB*HH)

// ---------------- scratch ----------------
#define SLICE (128*2560)
__device__ float  d_part[8*SLICE];
__device__ __align__(16) __half d_x_h[BB*HH];
__device__ __align__(16) __half d_cat_h[BB*H4];
__device__ __align__(16) __half d_nh_h[BB*LDG_NH];
__device__ float  d_logits[BB*LDG_LOG];
__device__ float  d_WlinT[H2*H2];

// ---------------- GEMM (tile 128x64, 2 CTAs/SM) ----------------
#define SROWB 144
#define AST   18432
#define WST   9216
#define OFF_W (2*AST)            // 36864
#define GSMEM (OFF_W + 2*WST)    // 55296

__device__ __forceinline__ uint32_t smem_u32_of(const void* p) {
    uint32_t a;
    asm("{ .reg .u64 t; cvta.to.shared.u64 t, %1; cvt.u32.u64 %0, t; }" : "=r"(a) : "l"(p));
    return a;
}
__device__ __forceinline__ void cp16(uint32_t saddr, const void* g) {
    asm volatile("cp.async.cg.shared.global [%0], [%1], 16;"
                 :: "r"(saddr), "l"(g));
}
__device__ __forceinline__ void cp_commit() { asm volatile("cp.async.commit_group;"); }
__device__ __forceinline__ void cp_wait1()  { asm volatile("cp.async.wait_group 1;"); }

__device__ __forceinline__ void ldsm_x4(uint32_t& r0, uint32_t& r1, uint32_t& r2, uint32_t& r3,
                                        uint32_t addr) {
    asm volatile("ldmatrix.sync.aligned.m8n8.x4.shared.b16 {%0,%1,%2,%3}, [%4];"
                 : "=r"(r0), "=r"(r1), "=r"(r2), "=r"(r3) : "r"(addr));
}
__device__ __forceinline__ void mma16816(float* c, const uint32_t* a, const uint32_t* b) {
    asm volatile("mma.sync.aligned.m16n8k16.row.col.f32.f16.f16.f32 "
                 "{%0,%1,%2,%3}, {%4,%5,%6,%7}, {%8,%9}, {%0,%1,%2,%3};"
                 : "+f"(c[0]), "+f"(c[1]), "+f"(c[2]), "+f"(c[3])
                 : "r"(a[0]), "r"(a[1]), "r"(a[2]), "r"(a[3]), "r"(b[0]), "r"(b[1]));
}

// C[128, 64-tile] = A[128,K](fp16) @ W[N,K]^T(fp32)
struct GemmCore {
    float acc[2][4][4];
    uint4  ra[4];
    float4 rw[4];
    int tid, lane, warp, wm, wn, n0;
    uint32_t sa, aPat, bPat;
    const __half* A; int lda;
    const float* W; int ldw;
    int N, K;
    char* smc;

    __device__ __forceinline__ void init(char* smc_, const __half* A_, int lda_,
                                         const float* W_, int ldw_, int n0_, int N_, int K_) {
        smc = smc_; A = A_; lda = lda_; W = W_; ldw = ldw_; n0 = n0_; N = N_; K = K_;
        tid = threadIdx.x; warp = tid >> 5; lane = tid & 31;
        wm = warp >> 1; wn = warp & 1;
        sa = smem_u32_of(smc);
        aPat = sa + (uint32_t)((wm*32 + (lane & 7) + ((lane >> 3) & 1)*8) * SROWB)
                  + (uint32_t)((lane >> 4) * 16);
        bPat = sa + (uint32_t)OFF_W
                  + (uint32_t)((wn*32 + (lane & 7) + (lane >> 4)*8) * SROWB)
                  + (uint32_t)(((lane >> 3) & 1) * 16);
        #pragma unroll
        for (int mi=0; mi<2; mi++)
            #pragma unroll
            for (int ni=0; ni<4; ni++)
                #pragma unroll
                for (int q=0; q<4; q++) acc[mi][ni][q] = 0.f;
    }

    __device__ __forceinline__ void ldg_tile(int kt) {
        const int k0 = kt * 64;
        #pragma unroll
        for (int i = 0; i < 4; i++) {
            int idx = tid + i*256;
            int row = idx >> 3, c = idx & 7;
            int gk = k0 + c*8;
            if (gk < K) ra[i] = *(const uint4*)(A + (size_t)row*lda + gk);
            else        ra[i] = make_uint4(0,0,0,0);
        }
        #pragma unroll
        for (int i = 0; i < 4; i++) {
            int idx = tid + i*256;
            int row = idx >> 4, c = idx & 15;
            int gk = k0 + c*4;
            int gn = n0 + row;
            if (gk < K && gn < N) rw[i] = *(const float4*)(W + (size_t)gn*ldw + gk);
            else                  rw[i] = make_float4(0.f,0.f,0.f,0.f);
        }
    }

    __device__ __forceinline__ void sts_tile(int s) {
        #pragma unroll
        for (int i = 0; i < 4; i++) {
            int idx = tid + i*256;
            int row = idx >> 3, c = idx & 7;
            *(uint4*)(smc + s*AST + row*SROWB + c*16) = ra[i];
        }
        #pragma unroll
        for (int i = 0; i < 4; i++) {
            int idx = tid + i*256;
            int row = idx >> 4, c = idx & 15;
            __half2 p0 = __floats2half2_rn(rw[i].x, rw[i].y);
            __half2 p1 = __floats2half2_rn(rw[i].z, rw[i].w);
            uint2 v; v.x = *(uint32_t*)&p0; v.y = *(uint32_t*)&p1;
            *(uint2*)(smc + OFF_W + s*WST + row*SROWB + c*8) = v;
        }
    }

    __device__ __forceinline__ void compute(int s) {
        const uint32_t aB = aPat + (uint32_t)(s*AST);
        const uint32_t bB = bPat + (uint32_t)(s*WST);
        #pragma unroll
        for (int ks = 0; ks < 4; ks++) {
            uint32_t af[2][4];
            #pragma unroll
            for (int mb = 0; mb < 2; mb++)
                ldsm_x4(af[mb][0], af[mb][1], af[mb][2], af[mb][3],
                        aB + (uint32_t)(mb*16*SROWB) + (uint32_t)(ks*32));
            uint32_t bf[4][2];
            #pragma unroll
            for (int nb2 = 0; nb2 < 2; nb2++) {
                uint32_t r0, r1, r2, r3;
                ldsm_x4(r0, r1, r2, r3,
                        bB + (uint32_t)(nb2*16*SROWB) + (uint32_t)(ks*32));
                bf[nb2*2+0][0] = r0; bf[nb2*2+0][1] = r1;
                bf[nb2*2+1][0] = r2; bf[nb2*2+1][1] = r3;
            }
            #pragma unroll
            for (int mi = 0; mi < 2; mi++)
                #pragma unroll
                for (int ni = 0; ni < 4; ni++)
                    mma16816(acc[mi][ni], af[mi], bf[ni]);
        }
    }

    // Single-barrier mainloop (hazard-safe; see R12)
    __device__ __forceinline__ void run(int kt0, int kt1) {
        ldg_tile(kt0);
        for (int kt = kt0; kt < kt1; kt++) {
            const int s = (kt - kt0) & 1;
            sts_tile(s);
            __syncthreads();
            if (kt + 1 < kt1) ldg_tile(kt + 1);
            compute(s);
        }
    }

    __device__ __forceinline__ void store(float* C, int ldc) {
        const int er = lane >> 2;
        const int ec = (lane & 3) * 2;
        #pragma unroll
        for (int mi = 0; mi < 2; mi++)
            #pragma unroll
            for (int ni = 0; ni < 4; ni++) {
                int row = wm*32 + mi*16 + er;
                int col = n0 + wn*32 + ni*8 + ec;
                float2 v0; v0.x = acc[mi][ni][0]; v0.y = acc[mi][ni][1];
                float2 v1; v1.x = acc[mi][ni][2]; v1.y = acc[mi][ni][3];
                *(float2*)(C + (size_t)row*ldc + col)     = v0;
                *(float2*)(C + (size_t)(row+8)*ldc + col) = v1;
            }
    }
};

// Direct GEMM (big W_soft)
__global__ void __launch_bounds__(256, 2) gemm_mma(
    const __half* __restrict__ A, int lda,
    const float* __restrict__ W, int ldw,
    float* __restrict__ C, int ldc, int N, int K)
{
    extern __shared__ __align__(16) char smc[];
    GemmCore g;
    g.init(smc, A, lda, W, ldw, blockIdx.x*64, N, K);
    g.run(0, (K + 63) >> 6);
    g.store(C, ldc);
}

// Split-K GEMM: grid (nx, nsplit, nW). Partial -> d_part slice (z*nsplit + y).
__global__ void __launch_bounds__(256, 2) gemm_mma_split(
    const __half* __restrict__ A, int lda,
    const float* __restrict__ W0, const float* __restrict__ W1, int ldw,
    int ldc, int N, int K)
{
    extern __shared__ __align__(16) char smc[];
    const float* W = blockIdx.z ? W1 : W0;
    const int nsplit = gridDim.y;
    const int KT = (K + 63) >> 6;
    const int kt0 = (KT * blockIdx.y) / nsplit;
    const int kt1 = (KT * (blockIdx.y + 1)) / nsplit;
    GemmCore g;
    g.init(smc, A, lda, W, ldw, blockIdx.x*64, N, K);
    g.run(kt0, kt1);
    const int slice = blockIdx.z * nsplit + blockIdx.y;
    g.store(d_part + (size_t)slice * SLICE, ldc);
}

// ---------------- transpose W_lin ----------------
__global__ void transpose_wlin(const float* __restrict__ Wl) {
    __shared__ float t[32][33];
    int x = blockIdx.x * 32 + threadIdx.x;
    int y = blockIdx.y * 32 + threadIdx.y;
    if (x < H2 && y < H2) t[threadIdx.y][threadIdx.x] = Wl[(size_t)y * H2 + x];
    __syncthreads();
    int ox = blockIdx.y * 32 + threadIdx.x;
    int oy = blockIdx.x * 32 + threadIdx.y;
    if (ox < H2 && oy < H2) d_WlinT[(size_t)oy * H2 + ox] = t[threadIdx.x][threadIdx.y];
}

// ---------------- small kernels ----------------
__device__ __forceinline__ float sigmoidf_(float x) { return 1.0f / (1.0f + __expf(-x)); }

__global__ void gather_emb(const int* __restrict__ word, const float* __restrict__ emb) {
    int idx = blockIdx.x*blockDim.x + threadIdx.x;
    if (idx >= BB*HH) return;
    int b = idx / HH, k = idx % HH;
    d_x_h[idx] = __float2half(emb[(size_t)word[b]*HH + k]);
}

// gates unsplit: slice z holds the full pre-bias gates for direction z
__global__ void lstm_act(const float* __restrict__ bihf, const float* __restrict__ bhhf,
                         const float* __restrict__ bihb, const float* __restrict__ bhhb,
                         float* __restrict__ out_cell) {
    int idx = blockIdx.x*blockDim.x + threadIdx.x;
    if (idx >= BB*HH) return;
    int b = idx / HH, j = idx % HH;
    #pragma unroll
    for (int z = 0; z < 2; z++) {
        const float* bih = z ? bihb : bihf;
        const float* bhh = z ? bhhb : bhhf;
        const float* g = d_part + (size_t)z*SLICE + (size_t)b*LDG_GATE;
        float i_ = g[j]        + bih[j]        + bhh[j];
        float gg = g[H2 + j]   + bih[H2 + j]   + bhh[H2 + j];
        float o_ = g[1800 + j] + bih[1800 + j] + bhh[1800 + j];
        float c = sigmoidf_(i_) * tanhf(gg);
        float h = sigmoidf_(o_) * tanhf(c);
        d_cat_h[b*H4 + z*HH + j] = __float2half(h);
        out_cell[z*BB*HH + b*HH + j] = c;
    }
}

// ---------------- flash attention, cp.async double-buffered chunk pipeline ----------------
#define AT2_CH     16
#define AT2_RSTR   1208                      // floats per row slot
#define AT2_BUF    (AT2_CH*AT2_RSTR)         // floats per buffer (19328)
#define AT2_OFF_SU  (2*AT2_BUF)              // 38656
#define AT2_OFF_SC  (AT2_OFF_SU + 1200)      // 39856
#define AT2_OFF_WT  (AT2_OFF_SC + 208)       // 40064
#define AT2_OFF_CTL (AT2_OFF_WT + 16)        // 40080
#define AT2_SMEM   ((AT2_OFF_CTL + 4) * 4)   // 160336 B
#define AT2_NC     ((RR + AT2_CH - 1)/AT2_CH) // 13

__global__ void __launch_bounds__(512) attn_flash(const float* __restrict__ enc,
                                                  float* __restrict__ log_att_out) {
    extern __shared__ float smf[];
    float* su     = smf + AT2_OFF_SU;
    float* sscore = smf + AT2_OFF_SC;
    float* swt    = smf + AT2_OFF_WT;
    float* sctl   = smf + AT2_OFF_CTL;   // [0]=factor, [1]=m, [2]=l
    const int b = blockIdx.x, tid = threadIdx.x;
    const int warp = tid >> 5, lane = tid & 31;
    const uint32_t sa = smem_u32_of(smf);

    // u[b] = sum of 8 split-K partials
    for (int k = tid; k < H2; k += 512) {
        float s = 0.f;
        #pragma unroll
        for (int p = 0; p < 8; p++) s += d_part[(size_t)p*SLICE + (size_t)b*LDG_U + k];
        su[k] = s;
    }
    if (tid == 0) { sctl[1] = -INFINITY; sctl[2] = 0.f; }

    // issue chunk 0 (no dependence on su)
    {
        const int nr0 = min(AT2_CH, RR);
        for (int idx = tid; idx < nr0*300; idx += 512) {
            int r = idx / 300, q = idx % 300;
            cp16(sa + (uint32_t)((r*AT2_RSTR + q*4)*4),
                 enc + ((size_t)b*RR + r)*H2 + q*4);
        }
        cp_commit();
    }
    __syncthreads();

    // lane-resident u slice
    float2 sureg[19];
    #pragma unroll
    for (int i = 0; i < 19; i++) {
        int j = lane + 32*i;
        sureg[i] = (j < 600) ? ((const float2*)su)[j] : make_float2(0.f, 0.f);
    }

    float2 acc0 = make_float2(0.f, 0.f), acc1 = make_float2(0.f, 0.f);
    const int d2a = tid;
    const int d2b = tid + 512;

    for (int c = 0; c < AT2_NC; c++) {
        // issue chunk c+1 into the other buffer (buf (c)&1 fully consumed at
        // the trailing barrier of iteration c-1, so (c+1)&1 is safe here)
        if (c + 1 < AT2_NC) {
            const int r0n = (c+1) * AT2_CH;
            const int nrn = min(AT2_CH, RR - r0n);
            const uint32_t base = sa + (uint32_t)((((c+1)&1)*AT2_BUF)*4);
            for (int idx = tid; idx < nrn*300; idx += 512) {
                int r = idx / 300, q = idx % 300;
                cp16(base + (uint32_t)((r*AT2_RSTR + q*4)*4),
                     enc + ((size_t)b*RR + r0n + r)*H2 + q*4);
            }
            cp_commit();
        } else {
            cp_commit();
        }
        cp_wait1();            // chunk c complete (exactly 1 newer group pending)
        __syncthreads();

        const int r0 = c * AT2_CH;
        const int nr = min(AT2_CH, RR - r0);
        float* srow = smf + (c&1)*AT2_BUF;

        // dots: warp w handles row w
        if (warp < nr) {
            const float2* row = (const float2*)(srow + warp*AT2_RSTR);
            float s = 0.f;
            #pragma unroll
            for (int i = 0; i < 19; i++) {
                int j = lane + 32*i;
                if (j < 600) {
                    float2 e = row[j];
                    s += e.x*sureg[i].x + e.y*sureg[i].y;
                }
            }
            #pragma unroll
            for (int o = 16; o > 0; o >>= 1) s += __shfl_xor_sync(0xFFFFFFFFu, s, o);
            if (lane == 0) sscore[r0 + warp] = s;
        }
        __syncthreads();

        // online softmax update (warp 0)
        if (warp == 0) {
            float m_old = sctl[1];
            float s = (lane < nr) ? sscore[r0 + lane] : -INFINITY;
            float cmax = s;
            #pragma unroll
            for (int o = 16; o > 0; o >>= 1)
                cmax = fmaxf(cmax, __shfl_xor_sync(0xFFFFFFFFu, cmax, o));
            float m_new = fmaxf(m_old, cmax);
            float w = (lane < nr) ? __expf(s - m_new) : 0.f;
            float csum = w;
            #pragma unroll
            for (int o = 16; o > 0; o >>= 1) csum += __shfl_xor_sync(0xFFFFFFFFu, csum, o);
            if (lane < AT2_CH) swt[lane] = w;
            if (lane == 0) {
                float l_old = sctl[2];
                float factor = __expf(m_old - m_new);
                sctl[0] = factor;
                sctl[1] = m_new;
                sctl[2] = l_old*factor + csum;
            }
        }
        __syncthreads();

        // accumulate selected from srow
        {
            float f = sctl[0];
            acc0.x *= f; acc0.y *= f; acc1.x *= f; acc1.y *= f;
            if (d2a < 600) {
                for (int r = 0; r < nr; r++) {
                    float wr = swt[r];
                    float2 e = ((const float2*)(srow + r*AT2_RSTR))[d2a];
                    acc0.x += wr*e.x; acc0.y += wr*e.y;
                }
            }
            if (d2b < 600) {
                for (int r = 0; r < nr; r++) {
                    float wr = swt[r];
                    float2 e = ((const float2*)(srow + r*AT2_RSTR))[d2b];
                    acc1.x += wr*e.x; acc1.y += wr*e.y;
                }
            }
        }
        __syncthreads();   // buffer consumed; safe for reuse at iter c+2's issue
    }

    const float lse = sctl[1] + logf(sctl[2]);
    const float inv = 1.f / sctl[2];
    for (int r = tid; r < RR; r += 512)
        log_att_out[(size_t)b*RR + r] = sscore[r] - lse;
    __half2* dst = (__half2*)(d_cat_h + (size_t)b*H4 + H2);
    if (d2a < 600) dst[d2a] = __floats2half2_rn(acc0.x*inv, acc0.y*inv);
    if (d2b < 600) dst[d2b] = __floats2half2_rn(acc1.x*inv, acc1.y*inv);
}

__global__ void nh_act(const float* __restrict__ b_tanh, float* __restrict__ nh_out) {
    int idx = blockIdx.x*blockDim.x + threadIdx.x;
    if (idx >= BB*H2) return;
    int b = idx / H2, j = idx % H2;
    float v = b_tanh[j];
    #pragma unroll
    for (int p = 0; p < 8; p++) v += d_part[(size_t)p*SLICE + (size_t)b*LDG_NH + j];
    v = tanhf(v);
    d_nh_h[(size_t)b*LDG_NH + j] = __float2half(v);
    int s = j / HH, hh = j % HH;
    nh_out[s*BB*HH + b*HH + hh] = v;
}

__global__ void pcopy_kernel(const float* __restrict__ W_sig, const float* __restrict__ b_sig,
                             float* __restrict__ out) {
    int w = (blockIdx.x*blockDim.x + threadIdx.x) >> 5;
    int lane = threadIdx.x & 31;
    if (w >= BB) return;
    const __half* nh = d_nh_h + (size_t)w*LDG_NH;
    float s = 0.f;
    for (int k = lane; k < H2; k += 32) s += __half2float(nh[k])*W_sig[k];
    #pragma unroll
    for (int o = 16; o > 0; o >>= 1) s += __shfl_xor_sync(0xFFFFFFFFu, s, o);
    if (lane == 0) out[w] = sigmoidf_(s + b_sig[0]);
}

#define LS_SMEM ((LDG_LOG + 1024) * 4)
__global__ void __launch_bounds__(1024) logsoftmax_v(const float* __restrict__ b_soft,
                                                     float* __restrict__ out) {
    extern __shared__ float sx[];
    float* red = sx + LDG_LOG;
    const int b = blockIdx.x, t = threadIdx.x;
    const float* x = d_logits + (size_t)b*LDG_LOG;
    float mx = -INFINITY;
    for (int v = t; v < VV; v += 1024) {
        float val = x[v] + b_soft[v];
        sx[v] = val;
        mx = fmaxf(mx, val);
    }
    red[t] = mx; __syncthreads();
    for (int s = 512; s > 0; s >>= 1) { if (t < s) red[t] = fmaxf(red[t], red[t+s]); __syncthreads(); }
    mx = red[0]; __syncthreads();
    float sum = 0.f;
    for (int v = t; v < VV; v += 1024) sum += __expf(sx[v] - mx);
    red[t] = sum; __syncthreads();
    for (int s = 512; s > 0; s >>= 1) { if (t < s) red[t] += red[t+s]; __syncthreads(); }
    float lse = mx + logf(red[0]);
    for (int v = t; v < VV; v += 1024) out[(size_t)b*VV + v] = sx[v] - lse;
}

// ---------------- launch ----------------
extern "C" void kernel_launch(void* const* d_in, const int* in_sizes, int n_in,
                              void* d_out, int out_size)
{
    const int*   word   = (const int*)  d_in[0];
    const float* enc    = (const float*)d_in[3];
    const float* emb    = (const float*)d_in[4];
    const float* W_ih_f = (const float*)d_in[5];
    const float* b_ih_f = (const float*)d_in[7];
    const float* b_hh_f = (const float*)d_in[8];
    const float* W_ih_b = (const float*)d_in[9];
    const float* b_ih_b = (const float*)d_in[11];
    const float* b_hh_b = (const float*)d_in[12];
    const float* W_lin  = (const float*)d_in[13];
    const float* W_tanh = (const float*)d_in[15];
    const float* b_tanh = (const float*)d_in[16];
    const float* W_soft = (const float*)d_in[17];
    const float* b_soft = (const float*)d_in[18];
    const float* W_sig  = (const float*)d_in[19];
    const float* b_sig  = (const float*)d_in[20];

    float* out = (float*)d_out;

    __half *px, *pcat, *pnh;
    float *plog, *pWlT;
    cudaGetSymbolAddress((void**)&px,   d_x_h);
    cudaGetSymbolAddress((void**)&pcat, d_cat_h);
    cudaGetSymbolAddress((void**)&pnh,  d_nh_h);
    cudaGetSymbolAddress((void**)&plog, d_logits);
    cudaGetSymbolAddress((void**)&pWlT, d_WlinT);

    cudaFuncSetAttribute(gemm_mma,       cudaFuncAttributeMaxDynamicSharedMemorySize, GSMEM);
    cudaFuncSetAttribute(gemm_mma_split, cudaFuncAttributeMaxDynamicSharedMemorySize, GSMEM);
    cudaFuncSetAttribute(logsoftmax_v,   cudaFuncAttributeMaxDynamicSharedMemorySize, LS_SMEM);
    cudaFuncSetAttribute(attn_flash,     cudaFuncAttributeMaxDynamicSharedMemorySize, AT2_SMEM);

    // 1. embedding gather + W_lin transpose
    gather_emb<<<(BB*HH + 255)/256, 256>>>(word, emb);
    transpose_wlin<<<dim3(38,38), dim3(32,32)>>>(W_lin);

    // 2. both gate GEMMs, unsplit (76 blocks, single 2-CTA/SM wave)
    gemm_mma_split<<<dim3(LDG_GATE/64,1,2), 256, GSMEM>>>(px, HH, W_ih_f, W_ih_b, HH,
                                                          LDG_GATE, H4, HH);

    // 3. LSTM activations
    lstm_act<<<(BB*HH + 255)/256, 256>>>(b_ih_f, b_hh_f, b_ih_b, b_hh_b, out + OFF_NEWCELL);

    // 4. u = h @ W_lin, split-K x8 (160 blocks)
    gemm_mma_split<<<dim3(LDG_U/64,8,1), 256, GSMEM>>>(pcat, H4, pWlT, pWlT, H2,
                                                       LDG_U, H2, H2);

    // 5. flash attention (cp.async double-buffered)
    attn_flash<<<BB, 512, AT2_SMEM>>>(enc, out + OFF_LOGATT);

    // 6. nh_raw = cat @ W_tanh^T, split-K x8 (160 blocks)
    gemm_mma_split<<<dim3(LDG_NH/64,8,1), 256, GSMEM>>>(pcat, H4, W_tanh, W_tanh, H4,
                                                        LDG_NH, H2, H4);

    // 7. nh activation + nh_out
    nh_act<<<(BB*H2 + 255)/256, 256>>>(b_tanh, out + OFF_NHOUT);

    // 8. p_copy
    pcopy_kernel<<<(BB*32 + 255)/256, 256>>>(W_sig, b_sig, out + OFF_PCOPY);

    // 9. logits = nh @ W_soft^T (786 blocks)
    gemm_mma<<<LDG_LOG/64, 256, GSMEM>>>(pnh, LDG_NH, W_soft, H2, plog, LDG_LOG, VV, H2);

    // 10. log_softmax over V (smem-cached)
    logsoftmax_v<<<BB, 1024, LS_SMEM>>>(b_soft, out + OFF_OUTPROB);
}